// round 2
// baseline (speedup 1.0000x reference)
#include <cuda_runtime.h>
#include <cstdint>

#define MTOT 32768   // B*L
#define DM   256
#define DI   384
#define DS   8

// ---------------- scratch (static device globals; no allocation) ----------------
__device__ float g_xn  [MTOT*DM];   // layernorm output, tf32-rounded
__device__ float g_xp  [MTOT*DI];   // silu(x_proj), fp32
__device__ float g_z   [MTOT*DI];   // silu(z), fp32
__device__ float g_dtin[MTOT*DI];   // dt_in, tf32-rounded
__device__ float g_dt  [MTOT*DI];   // softplus(dt), fp32
__device__ float g_ymod[MTOT*DI];   // y*z + xp*D, tf32-rounded
__device__ float g_win [3*DI*DM];   // tf32-rounded weights
__device__ float g_wdt [DI*DI];
__device__ float g_wout[DM*DI];
__device__ float g_a2  [DI*DS];     // -exp(A_log) * log2(e)

// ---------------- helpers ----------------
__device__ __forceinline__ float tf32r(float x){
    uint32_t u; asm("cvt.rna.tf32.f32 %0, %1;" : "=r"(u) : "f"(x));
    return __uint_as_float(u);
}
__device__ __forceinline__ float ex2f(float x){
    float r; asm("ex2.approx.f32 %0, %1;" : "=f"(r) : "f"(x)); return r;
}
__device__ __forceinline__ float siluf(float x){
    return x / (1.f + __expf(-x));
}
__device__ __forceinline__ float softplusf(float x){
    return fmaxf(x, 0.f) + log1pf(__expf(-fabsf(x)));
}

// ---------------- weight prep: tf32-round weights, build A*log2e ----------------
__global__ void prep_kernel(const float* __restrict__ W_in, const float* __restrict__ W_dt,
                            const float* __restrict__ W_out, const float* __restrict__ A_log){
    int i = blockIdx.x*256 + threadIdx.x;
    if (i < 3*DI*DM) g_win[i]  = tf32r(W_in[i]);
    if (i < DI*DI)   g_wdt[i]  = tf32r(W_dt[i]);
    if (i < DM*DI)   g_wout[i] = tf32r(W_out[i]);
    if (i < DI*DS)   g_a2[i]   = -expf(A_log[i]) * 1.4426950408889634f;
}

// ---------------- layernorm: 1 warp per 256-wide row ----------------
__global__ void ln_kernel(const float* __restrict__ x, const float* __restrict__ gamma,
                          const float* __restrict__ beta){
    int row  = blockIdx.x*8 + (threadIdx.x>>5);
    int lane = threadIdx.x & 31;
    const float4* xr = (const float4*)(x + (size_t)row*DM);
    float4 v0 = xr[lane];
    float4 v1 = xr[32+lane];
    float s = v0.x+v0.y+v0.z+v0.w + v1.x+v1.y+v1.z+v1.w;
    float q = v0.x*v0.x+v0.y*v0.y+v0.z*v0.z+v0.w*v0.w
            + v1.x*v1.x+v1.y*v1.y+v1.z*v1.z+v1.w*v1.w;
    #pragma unroll
    for (int o=16;o;o>>=1){ s += __shfl_xor_sync(~0u,s,o); q += __shfl_xor_sync(~0u,q,o); }
    float mu  = s * (1.f/DM);
    float var = q * (1.f/DM) - mu*mu;
    float rs  = rsqrtf(var + 1e-5f);
    const float4* g4 = (const float4*)gamma;
    const float4* b4 = (const float4*)beta;
    float4 g0=g4[lane], g1=g4[32+lane], e0=b4[lane], e1=b4[32+lane];
    float4 r0, r1;
    r0.x = tf32r((v0.x-mu)*rs*g0.x + e0.x);
    r0.y = tf32r((v0.y-mu)*rs*g0.y + e0.y);
    r0.z = tf32r((v0.z-mu)*rs*g0.z + e0.z);
    r0.w = tf32r((v0.w-mu)*rs*g0.w + e0.w);
    r1.x = tf32r((v1.x-mu)*rs*g1.x + e1.x);
    r1.y = tf32r((v1.y-mu)*rs*g1.y + e1.y);
    r1.z = tf32r((v1.z-mu)*rs*g1.z + e1.z);
    r1.w = tf32r((v1.w-mu)*rs*g1.w + e1.w);
    float4* o = (float4*)(g_xn + (size_t)row*DM);
    o[lane]    = r0;
    o[32+lane] = r1;
}

// ---------------- tf32 mma GEMM (C[M,N] = A[M,K] @ W[N,K]^T), fused epilogues ----------------
#define BM 128
#define BN 128
#define BK 32
#define KPAD 4

__device__ __forceinline__ void mma_tf32(float c[4], const uint32_t a[4], const uint32_t b[2]){
    asm volatile("mma.sync.aligned.m16n8k8.row.col.f32.tf32.tf32.f32 "
        "{%0,%1,%2,%3},{%4,%5,%6,%7},{%8,%9},{%0,%1,%2,%3};"
        : "+f"(c[0]), "+f"(c[1]), "+f"(c[2]), "+f"(c[3])
        : "r"(a[0]), "r"(a[1]), "r"(a[2]), "r"(a[3]), "r"(b[0]), "r"(b[1]));
}

// MODE 0: xn @ W_in^T + b_in -> silu->g_xp | silu->g_z | tf32->g_dtin
// MODE 1: dtin @ W_dt^T + b_dt -> softplus -> g_dt
// MODE 2: ymod @ W_out^T + b_out + residual -> out
template<int MODE>
__global__ __launch_bounds__(256)
void gemm_kernel(const float* __restrict__ bias, const float* __restrict__ extra,
                 float* __restrict__ out){
    constexpr int N = (MODE==0) ? 3*DI : (MODE==1) ? DI : DM;
    constexpr int K = (MODE==0) ? DM : DI;
    const float* __restrict__ A  = (MODE==0) ? g_xn  : (MODE==1) ? g_dtin : g_ymod;
    const float* __restrict__ Bw = (MODE==0) ? g_win : (MODE==1) ? g_wdt  : g_wout;

    __shared__ float As[BM][BK+KPAD];
    __shared__ float Bs[BN][BK+KPAD];

    int tid  = threadIdx.x;
    int warp = tid>>5, lane = tid&31;
    int wm   = warp&3, wn  = warp>>2;        // 4 x 2 warps -> 32x64 warp tile
    int grp  = lane>>2, t4 = lane&3;
    int bm   = blockIdx.y*BM, bn = blockIdx.x*BN;

    float acc[2][8][4];
    #pragma unroll
    for (int i=0;i<2;i++)
        #pragma unroll
        for (int j=0;j<8;j++)
            #pragma unroll
            for (int k=0;k<4;k++) acc[i][j][k]=0.f;

    // register prefetch of first tile
    float4 ra[4], rb[4];
    #pragma unroll
    for (int i=0;i<4;i++){
        int idx = tid + i*256;
        int r = idx>>3, c = (idx&7)<<2;
        ra[i] = *(const float4*)&A [(size_t)(bm+r)*K + c];
        rb[i] = *(const float4*)&Bw[(size_t)(bn+r)*K + c];
    }

    for (int k0=0;k0<K;k0+=BK){
        #pragma unroll
        for (int i=0;i<4;i++){
            int idx = tid + i*256;
            int r = idx>>3, c = (idx&7)<<2;
            *(float4*)&As[r][c] = ra[i];
            *(float4*)&Bs[r][c] = rb[i];
        }
        __syncthreads();
        if (k0 + BK < K){
            #pragma unroll
            for (int i=0;i<4;i++){
                int idx = tid + i*256;
                int r = idx>>3, c = (idx&7)<<2;
                ra[i] = *(const float4*)&A [(size_t)(bm+r)*K + k0 + BK + c];
                rb[i] = *(const float4*)&Bw[(size_t)(bn+r)*K + k0 + BK + c];
            }
        }
        #pragma unroll
        for (int kk=0;kk<BK;kk+=8){
            uint32_t af[2][4], bf[8][2];
            #pragma unroll
            for (int mi=0;mi<2;mi++){
                int r = wm*32 + mi*16 + grp;
                af[mi][0] = __float_as_uint(As[r  ][kk+t4]);
                af[mi][1] = __float_as_uint(As[r+8][kk+t4]);
                af[mi][2] = __float_as_uint(As[r  ][kk+t4+4]);
                af[mi][3] = __float_as_uint(As[r+8][kk+t4+4]);
            }
            #pragma unroll
            for (int ni=0;ni<8;ni++){
                int rn = wn*64 + ni*8 + grp;
                bf[ni][0] = __float_as_uint(Bs[rn][kk+t4]);
                bf[ni][1] = __float_as_uint(Bs[rn][kk+t4+4]);
            }
            #pragma unroll
            for (int mi=0;mi<2;mi++)
                #pragma unroll
                for (int ni=0;ni<8;ni++)
                    mma_tf32(acc[mi][ni], af[mi], bf[ni]);
        }
        __syncthreads();
    }

    // epilogue
    #pragma unroll
    for (int mi=0;mi<2;mi++){
        #pragma unroll
        for (int ni=0;ni<8;ni++){
            int r0 = bm + wm*32 + mi*16 + grp;
            int c0 = bn + wn*64 + ni*8 + 2*t4;
            #pragma unroll
            for (int h=0;h<2;h++){
                int r = r0 + h*8;
                float v0 = acc[mi][ni][2*h]   + bias[c0];
                float v1 = acc[mi][ni][2*h+1] + bias[c0+1];
                if (MODE==0){
                    if (c0 < DI){
                        *(float2*)&g_xp[(size_t)r*DI + c0] = make_float2(siluf(v0), siluf(v1));
                    } else if (c0 < 2*DI){
                        *(float2*)&g_z [(size_t)r*DI + c0 - DI] = make_float2(siluf(v0), siluf(v1));
                    } else {
                        *(float2*)&g_dtin[(size_t)r*DI + c0 - 2*DI] = make_float2(tf32r(v0), tf32r(v1));
                    }
                } else if (MODE==1){
                    *(float2*)&g_dt[(size_t)r*DI + c0] = make_float2(softplusf(v0), softplusf(v1));
                } else {
                    float2 e = *(const float2*)&extra[(size_t)r*DM + c0];
                    *(float2*)&out[(size_t)r*DM + c0] = make_float2(v0 + e.x, v1 + e.y);
                }
            }
        }
    }
}

// ---------------- chunked scan + gating: one thread per (b, chunk, channel) ----------------
__global__ __launch_bounds__(384)
void scan_kernel(const float* __restrict__ D_vec){
    int d  = threadIdx.x;              // 0..383
    int bc = blockIdx.x;               // 0..1023  (b*128 + chunk)
    size_t base = (size_t)bc*32*DI + d;
    float Av[DS];
    #pragma unroll
    for (int s=0;s<DS;s++) Av[s] = g_a2[d*DS + s];
    float Dd = D_vec[d];
    float h[DS];
    #pragma unroll
    for (int s=0;s<DS;s++) h[s] = 0.f;
    #pragma unroll 4
    for (int t=0;t<32;t++){
        size_t off = base + (size_t)t*DI;
        float xv  = g_xp[off];
        float dtv = g_dt[off];
        float zv  = g_z [off];
        float y = 0.f;
        #pragma unroll
        for (int s=0;s<DS;s++){
            float e = ex2f(dtv * Av[s]);   // exp(dt*A) via exp2(dt*A*log2e)
            h[s] = fmaf(h[s], e, xv);
            y += h[s];
        }
        g_ymod[off] = tf32r(fmaf(y, zv, xv*Dd));
    }
}

// ---------------- launch ----------------
extern "C" void kernel_launch(void* const* d_in, const int* in_sizes, int n_in,
                              void* d_out, int out_size){
    const float* x     = (const float*)d_in[0];
    const float* gamma = (const float*)d_in[1];
    const float* beta  = (const float*)d_in[2];
    const float* W_in  = (const float*)d_in[3];
    const float* b_in  = (const float*)d_in[4];
    const float* W_dt  = (const float*)d_in[5];
    const float* b_dt  = (const float*)d_in[6];
    const float* A_log = (const float*)d_in[7];
    const float* D_vec = (const float*)d_in[8];
    const float* W_out = (const float*)d_in[9];
    const float* b_out = (const float*)d_in[10];
    float* out = (float*)d_out;

    prep_kernel<<<(3*DI*DM + 255)/256, 256>>>(W_in, W_dt, W_out, A_log);
    ln_kernel<<<MTOT/8, 256>>>(x, gamma, beta);
    gemm_kernel<0><<<dim3(3*DI/BN, MTOT/BM), 256>>>(b_in, nullptr, nullptr);
    gemm_kernel<1><<<dim3(DI/BN,   MTOT/BM), 256>>>(b_dt, nullptr, nullptr);
    scan_kernel<<<MTOT/32, DI>>>(D_vec);
    gemm_kernel<2><<<dim3(DM/BN,   MTOT/BM), 256>>>(b_out, x, out);
}

// round 13
// speedup vs baseline: 1.3251x; 1.3251x over previous
#include <cuda_runtime.h>
#include <cstdint>

#define MTOT 32768   // B*L
#define DM   256
#define DI   384
#define DS   8

// ---------------- scratch (static device globals; no allocation) ----------------
__device__ float g_xn  [MTOT*DM];   // layernorm output, tf32-rounded
__device__ float g_xp  [MTOT*DI];   // silu(x_proj), fp32
__device__ float g_z   [MTOT*DI];   // silu(z), fp32
__device__ float g_dtin[MTOT*DI];   // dt_in, tf32-rounded
__device__ float g_dt  [MTOT*DI];   // softplus(dt), fp32
__device__ float g_ymod[MTOT*DI];   // y*z + xp*D, tf32-rounded
__device__ float g_win [3*DI*DM];   // tf32-rounded weights
__device__ float g_wdt [DI*DI];
__device__ float g_wout[DM*DI];
__device__ float g_a2  [DI*DS];     // -exp(A_log) * log2(e)

// ---------------- helpers ----------------
__device__ __forceinline__ float tf32r(float x){
    uint32_t u; asm("cvt.rna.tf32.f32 %0, %1;" : "=r"(u) : "f"(x));
    return __uint_as_float(u);
}
__device__ __forceinline__ float ex2f(float x){
    float r; asm("ex2.approx.f32 %0, %1;" : "=f"(r) : "f"(x)); return r;
}
__device__ __forceinline__ float siluf(float x){
    return x / (1.f + __expf(-x));
}
__device__ __forceinline__ float softplusf(float x){
    return fmaxf(x, 0.f) + log1pf(__expf(-fabsf(x)));
}
__device__ __forceinline__ void cp_async16(uint32_t saddr, const void* gptr){
    asm volatile("cp.async.ca.shared.global [%0], [%1], 16;" :: "r"(saddr), "l"(gptr));
}

// ---------------- weight prep ----------------
__global__ void prep_kernel(const float* __restrict__ W_in, const float* __restrict__ W_dt,
                            const float* __restrict__ W_out, const float* __restrict__ A_log){
    int i = blockIdx.x*256 + threadIdx.x;
    if (i < 3*DI*DM) g_win[i]  = tf32r(W_in[i]);
    if (i < DI*DI)   g_wdt[i]  = tf32r(W_dt[i]);
    if (i < DM*DI)   g_wout[i] = tf32r(W_out[i]);
    if (i < DI*DS)   g_a2[i]   = -expf(A_log[i]) * 1.4426950408889634f;
}

// ---------------- layernorm: 1 warp per 256-wide row ----------------
__global__ void ln_kernel(const float* __restrict__ x, const float* __restrict__ gamma,
                          const float* __restrict__ beta){
    int row  = blockIdx.x*8 + (threadIdx.x>>5);
    int lane = threadIdx.x & 31;
    const float4* xr = (const float4*)(x + (size_t)row*DM);
    float4 v0 = xr[lane];
    float4 v1 = xr[32+lane];
    float s = v0.x+v0.y+v0.z+v0.w + v1.x+v1.y+v1.z+v1.w;
    float q = v0.x*v0.x+v0.y*v0.y+v0.z*v0.z+v0.w*v0.w
            + v1.x*v1.x+v1.y*v1.y+v1.z*v1.z+v1.w*v1.w;
    #pragma unroll
    for (int o=16;o;o>>=1){ s += __shfl_xor_sync(~0u,s,o); q += __shfl_xor_sync(~0u,q,o); }
    float mu  = s * (1.f/DM);
    float var = q * (1.f/DM) - mu*mu;
    float rs  = rsqrtf(var + 1e-5f);
    const float4* g4 = (const float4*)gamma;
    const float4* b4 = (const float4*)beta;
    float4 g0=g4[lane], g1=g4[32+lane], e0=b4[lane], e1=b4[32+lane];
    float4 r0, r1;
    r0.x = tf32r((v0.x-mu)*rs*g0.x + e0.x);
    r0.y = tf32r((v0.y-mu)*rs*g0.y + e0.y);
    r0.z = tf32r((v0.z-mu)*rs*g0.z + e0.z);
    r0.w = tf32r((v0.w-mu)*rs*g0.w + e0.w);
    r1.x = tf32r((v1.x-mu)*rs*g1.x + e1.x);
    r1.y = tf32r((v1.y-mu)*rs*g1.y + e1.y);
    r1.z = tf32r((v1.z-mu)*rs*g1.z + e1.z);
    r1.w = tf32r((v1.w-mu)*rs*g1.w + e1.w);
    float4* o = (float4*)(g_xn + (size_t)row*DM);
    o[lane]    = r0;
    o[32+lane] = r1;
}

// ---------------- tf32 mma GEMM, 2-stage cp.async pipeline ----------------
#define BM 128
#define BN 128
#define BK 32
#define LDS_W (BK+4)                      // padded row stride (floats)
#define STAGE_FLTS ((BM+BN)*LDS_W)        // floats per stage
#define SMEM_BYTES (2*STAGE_FLTS*4)       // 73728

__device__ __forceinline__ void mma_tf32(float c[4], const uint32_t a[4], const uint32_t b[2]){
    asm volatile("mma.sync.aligned.m16n8k8.row.col.f32.tf32.tf32.f32 "
        "{%0,%1,%2,%3},{%4,%5,%6,%7},{%8,%9},{%0,%1,%2,%3};"
        : "+f"(c[0]), "+f"(c[1]), "+f"(c[2]), "+f"(c[3])
        : "r"(a[0]), "r"(a[1]), "r"(a[2]), "r"(a[3]), "r"(b[0]), "r"(b[1]));
}

// MODE 0: xn @ W_in^T + b_in -> silu->g_xp | silu->g_z | tf32->g_dtin
// MODE 1: dtin @ W_dt^T + b_dt -> softplus -> g_dt
// MODE 2: ymod @ W_out^T + b_out + residual -> out
template<int MODE>
__global__ __launch_bounds__(256, 2)
void gemm_kernel(const float* __restrict__ bias, const float* __restrict__ extra,
                 float* __restrict__ out){
    constexpr int K = (MODE==0) ? DM : DI;
    const float* __restrict__ A  = (MODE==0) ? g_xn  : (MODE==1) ? g_dtin : g_ymod;
    const float* __restrict__ Bw = (MODE==0) ? g_win : (MODE==1) ? g_wdt  : g_wout;

    extern __shared__ float smem[];
    uint32_t smem_u32 = (uint32_t)__cvta_generic_to_shared(smem);

    int tid  = threadIdx.x;
    int warp = tid>>5, lane = tid&31;
    int wm   = warp&3, wn  = warp>>2;        // 4 x 2 warps -> 32x64 warp tile
    int grp  = lane>>2, t4 = lane&3;
    int bm   = blockIdx.y*BM, bn = blockIdx.x*BN;

    // per-thread copy coordinates: 4 rows-of-8 chunks for A, 4 for B
    int cr = tid>>3;               // 0..31
    int cc = (tid&7)<<2;           // 0,4,...,28

    float acc[2][8][4];
    #pragma unroll
    for (int i=0;i<2;i++)
        #pragma unroll
        for (int j=0;j<8;j++)
            #pragma unroll
            for (int k=0;k<4;k++) acc[i][j][k]=0.f;

    // issue one stage of cp.async copies
    auto issue = [&](int s, int k0){
        uint32_t base = smem_u32 + (uint32_t)s*STAGE_FLTS*4;
        #pragma unroll
        for (int i=0;i<4;i++){
            int r = cr + i*32;
            cp_async16(base + (uint32_t)(r*LDS_W + cc)*4,
                       &A[(size_t)(bm+r)*K + k0 + cc]);
        }
        #pragma unroll
        for (int i=0;i<4;i++){
            int r = cr + i*32;
            cp_async16(base + (uint32_t)((BM+r)*LDS_W + cc)*4,
                       &Bw[(size_t)(bn+r)*K + k0 + cc]);
        }
        asm volatile("cp.async.commit_group;");
    };

    issue(0, 0);

    constexpr int NIT = K/BK;
    #pragma unroll 1
    for (int it=0; it<NIT; ++it){
        int s = it & 1;
        if (it+1 < NIT){
            issue(s^1, (it+1)*BK);
            asm volatile("cp.async.wait_group 1;");
        } else {
            asm volatile("cp.async.wait_group 0;");
        }
        __syncthreads();

        const float* As = smem + s*STAGE_FLTS;
        const float* Bs = As + BM*LDS_W;

        #pragma unroll
        for (int kk=0;kk<BK;kk+=8){
            uint32_t af[2][4], bf[8][2];
            #pragma unroll
            for (int mi=0;mi<2;mi++){
                int r = wm*32 + mi*16 + grp;
                af[mi][0] = __float_as_uint(As[r*LDS_W     + kk+t4]);
                af[mi][1] = __float_as_uint(As[(r+8)*LDS_W + kk+t4]);
                af[mi][2] = __float_as_uint(As[r*LDS_W     + kk+t4+4]);
                af[mi][3] = __float_as_uint(As[(r+8)*LDS_W + kk+t4+4]);
            }
            #pragma unroll
            for (int ni=0;ni<8;ni++){
                int rn = wn*64 + ni*8 + grp;
                bf[ni][0] = __float_as_uint(Bs[rn*LDS_W + kk+t4]);
                bf[ni][1] = __float_as_uint(Bs[rn*LDS_W + kk+t4+4]);
            }
            #pragma unroll
            for (int mi=0;mi<2;mi++)
                #pragma unroll
                for (int ni=0;ni<8;ni++)
                    mma_tf32(acc[mi][ni], af[mi], bf[ni]);
        }
        __syncthreads();
    }

    // epilogue
    #pragma unroll
    for (int mi=0;mi<2;mi++){
        #pragma unroll
        for (int ni=0;ni<8;ni++){
            int r0 = bm + wm*32 + mi*16 + grp;
            int c0 = bn + wn*64 + ni*8 + 2*t4;
            #pragma unroll
            for (int h=0;h<2;h++){
                int r = r0 + h*8;
                float v0 = acc[mi][ni][2*h]   + bias[c0];
                float v1 = acc[mi][ni][2*h+1] + bias[c0+1];
                if (MODE==0){
                    if (c0 < DI){
                        *(float2*)&g_xp[(size_t)r*DI + c0] = make_float2(siluf(v0), siluf(v1));
                    } else if (c0 < 2*DI){
                        *(float2*)&g_z [(size_t)r*DI + c0 - DI] = make_float2(siluf(v0), siluf(v1));
                    } else {
                        *(float2*)&g_dtin[(size_t)r*DI + c0 - 2*DI] = make_float2(tf32r(v0), tf32r(v1));
                    }
                } else if (MODE==1){
                    *(float2*)&g_dt[(size_t)r*DI + c0] = make_float2(softplusf(v0), softplusf(v1));
                } else {
                    float2 e = *(const float2*)&extra[(size_t)r*DM + c0];
                    *(float2*)&out[(size_t)r*DM + c0] = make_float2(v0 + e.x, v1 + e.y);
                }
            }
        }
    }
}

// ---------------- chunked scan + gating ----------------
__global__ __launch_bounds__(384)
void scan_kernel(const float* __restrict__ D_vec){
    int d  = threadIdx.x;              // 0..383
    int bc = blockIdx.x;               // 0..1023  (b*128 + chunk)
    size_t base = (size_t)bc*32*DI + d;
    float Av[DS];
    #pragma unroll
    for (int s=0;s<DS;s++) Av[s] = g_a2[d*DS + s];
    float Dd = D_vec[d];
    float h[DS];
    #pragma unroll
    for (int s=0;s<DS;s++) h[s] = 0.f;
    #pragma unroll 4
    for (int t=0;t<32;t++){
        size_t off = base + (size_t)t*DI;
        float xv  = g_xp[off];
        float dtv = g_dt[off];
        float zv  = g_z [off];
        float y = 0.f;
        #pragma unroll
        for (int s=0;s<DS;s++){
            float e = ex2f(dtv * Av[s]);   // exp(dt*A) via exp2(dt*A*log2e)
            h[s] = fmaf(h[s], e, xv);
            y += h[s];
        }
        g_ymod[off] = tf32r(fmaf(y, zv, xv*Dd));
    }
}

// ---------------- launch ----------------
extern "C" void kernel_launch(void* const* d_in, const int* in_sizes, int n_in,
                              void* d_out, int out_size){
    const float* x     = (const float*)d_in[0];
    const float* gamma = (const float*)d_in[1];
    const float* beta  = (const float*)d_in[2];
    const float* W_in  = (const float*)d_in[3];
    const float* b_in  = (const float*)d_in[4];
    const float* W_dt  = (const float*)d_in[5];
    const float* b_dt  = (const float*)d_in[6];
    const float* A_log = (const float*)d_in[7];
    const float* D_vec = (const float*)d_in[8];
    const float* W_out = (const float*)d_in[9];
    const float* b_out = (const float*)d_in[10];
    float* out = (float*)d_out;

    // idempotent, non-stream API (capture-safe); no static guards per harness rules
    cudaFuncSetAttribute(gemm_kernel<0>, cudaFuncAttributeMaxDynamicSharedMemorySize, SMEM_BYTES);
    cudaFuncSetAttribute(gemm_kernel<1>, cudaFuncAttributeMaxDynamicSharedMemorySize, SMEM_BYTES);
    cudaFuncSetAttribute(gemm_kernel<2>, cudaFuncAttributeMaxDynamicSharedMemorySize, SMEM_BYTES);

    prep_kernel<<<(3*DI*DM + 255)/256, 256>>>(W_in, W_dt, W_out, A_log);
    ln_kernel<<<MTOT/8, 256>>>(x, gamma, beta);
    gemm_kernel<0><<<dim3(3*DI/BN, MTOT/BM), 256, SMEM_BYTES>>>(b_in, nullptr, nullptr);
    gemm_kernel<1><<<dim3(DI/BN,   MTOT/BM), 256, SMEM_BYTES>>>(b_dt, nullptr, nullptr);
    scan_kernel<<<MTOT/32, DI>>>(D_vec);
    gemm_kernel<2><<<dim3(DM/BN,   MTOT/BM), 256, SMEM_BYTES>>>(b_out, x, out);
}